// round 4
// baseline (speedup 1.0000x reference)
#include <cuda_runtime.h>
#include <math.h>

#define BB 8
#define NN 4096
#define KK 20
#define BN (BB*NN)

// ---------------- scratch (static device globals; no runtime alloc) ----------------
__device__ float g_x0[BN*6];
__device__ float g_xcat[(size_t)BN*512];
__device__ float g_A[(size_t)BN*256];
__device__ float g_C[(size_t)BN*256];
__device__ float g_sq[BN];
__device__ int   g_knn[BN*KK];
__device__ int   g_pool_enc[BB*1024];
__device__ float g_h1[BB*512];
__device__ float g_h2[BB*256];

__device__ __forceinline__ int   encf(float f){ int i=__float_as_int(f); return i>=0 ? i : i^0x7FFFFFFF; }
__device__ __forceinline__ float decf(int i){ return __int_as_float(i>=0 ? i : i^0x7FFFFFFF); }
#define ENC_NEG_INF (-2139095041)  /* encf(-inf) = 0x807FFFFF */

// ---------------- build x0 = concat(pos, x) ----------------
__global__ void build_x0_kernel(const float* __restrict__ pos, const float* __restrict__ x) {
    int g = blockIdx.x * 256 + threadIdx.x;
    if (g >= BN*6) return;
    int n = g / 6, c = g - n*6;
    g_x0[g] = (c < 3) ? pos[n*3 + c] : x[n*3 + c - 3];
}

__global__ void init_pool_kernel() {
    int g = blockIdx.x * 256 + threadIdx.x;
    if (g < BB*1024) g_pool_enc[g] = ENC_NEG_INF;
}

// ---------------- squared norms ----------------
template<int CIN, int SIN, bool USE_X0, int INOFF>
__global__ void sq_kernel() {
    int g = blockIdx.x * 256 + threadIdx.x;
    if (g >= BN) return;
    const float* base = USE_X0 ? g_x0 : (g_xcat + INOFF);
    const float* xr = base + (size_t)g * SIN;
    float s = 0.f;
    #pragma unroll 8
    for (int c = 0; c < CIN; c++) { float v = xr[c]; s += v*v; }
    g_sq[g] = s;
}

// ---------------- kNN: streaming top-20 over tiled gram matrix ----------------
template<int CIN, int SIN, bool USE_X0, int INOFF>
__global__ void __launch_bounds__(128) knn_kernel() {
    const int b   = blockIdx.y;
    const int tid = threadIdx.x;
    const int i   = blockIdx.x * 128 + tid;
    const float* base = USE_X0 ? g_x0 : (g_xcat + INOFF);
    const float* Xb = base + (size_t)b * NN * SIN;

    __shared__ float Xjs[32][CIN];
    __shared__ float sqj[32];

    float kd[KK]; int ki[KK];
    #pragma unroll
    for (int k = 0; k < KK; k++) { kd[k] = 3.4e38f; ki[k] = 0; }
    float worst = 3.4e38f;

    const float sqi = g_sq[b*NN + i];
    const float* xi = Xb + (size_t)i * SIN;

    for (int jb = 0; jb < NN; jb += 32) {
        __syncthreads();
        for (int e = tid; e < 32*CIN; e += 128) {
            int r = e / CIN, c = e - r*CIN;
            Xjs[r][c] = Xb[(size_t)(jb + r)*SIN + c];
        }
        if (tid < 32) sqj[tid] = g_sq[b*NN + jb + tid];
        __syncthreads();

        float acc[32];
        #pragma unroll
        for (int j = 0; j < 32; j++) acc[j] = 0.f;

        if (CIN % 4 == 0) {
            #pragma unroll 2
            for (int c4 = 0; c4 < CIN/4; c4++) {
                const float4 a4 = *reinterpret_cast<const float4*>(xi + c4*4);
                #pragma unroll
                for (int j = 0; j < 32; j++) {
                    const float4 b4 = *reinterpret_cast<const float4*>(&Xjs[j][c4*4]);
                    acc[j] = fmaf(a4.x, b4.x, acc[j]);
                    acc[j] = fmaf(a4.y, b4.y, acc[j]);
                    acc[j] = fmaf(a4.z, b4.z, acc[j]);
                    acc[j] = fmaf(a4.w, b4.w, acc[j]);
                }
            }
        } else {
            #pragma unroll
            for (int c = 0; c < CIN; c++) {
                float xv = xi[c];
                #pragma unroll
                for (int j = 0; j < 32; j++) acc[j] = fmaf(xv, Xjs[j][c], acc[j]);
            }
        }

        #pragma unroll
        for (int j = 0; j < 32; j++) {
            float d = sqi + sqj[j] - 2.f*acc[j];
            if (d < worst) {
                int p = KK - 1;
                while (p > 0 && kd[p-1] > d) { kd[p] = kd[p-1]; ki[p] = ki[p-1]; p--; }
                kd[p] = d; ki[p] = jb + j;
                worst = kd[KK-1];
            }
        }
    }
    int* dst = g_knn + (size_t)(b*NN + i)*KK;
    #pragma unroll
    for (int k = 0; k < KK; k++) dst[k] = ki[k];
}

// ---------------- per-node projections: A = X(Wt-Wb)+b, C = X Wb ----------------
template<int CIN, int SIN, bool USE_X0, int INOFF, int COUT>
__global__ void __launch_bounds__(256) proj_kernel(const float* __restrict__ W,
                                                   const float* __restrict__ bias) {
    constexpr int TM = 16;
    constexpr int STRIP = COUT / 16;        // 4, 8, or 16 (all %4==0)
    __shared__ float xs[TM][CIN];

    const int nodeBase = blockIdx.x * TM;
    const int tid = threadIdx.x;
    const float* base = USE_X0 ? g_x0 : (g_xcat + INOFF);

    for (int e = tid; e < TM*CIN; e += 256) {
        int r = e / CIN, c = e - r*CIN;
        xs[r][c] = base[(size_t)(nodeBase + r)*SIN + c];
    }
    __syncthreads();

    const int node = tid >> 4;
    const int cg   = tid & 15;
    const int co   = cg * STRIP;

    float accA[STRIP], accC[STRIP];
    #pragma unroll
    for (int s = 0; s < STRIP; s++) { accA[s] = 0.f; accC[s] = 0.f; }

    #pragma unroll 4
    for (int c = 0; c < CIN; c++) {
        float xv = xs[node][c];
        const float4* wt = reinterpret_cast<const float4*>(W + (size_t)c*COUT + co);
        const float4* wb = reinterpret_cast<const float4*>(W + (size_t)(CIN + c)*COUT + co);
        #pragma unroll
        for (int u = 0; u < STRIP/4; u++) {
            float4 t4 = __ldg(wt + u);
            float4 b4 = __ldg(wb + u);
            accA[4*u+0] = fmaf(xv, t4.x - b4.x, accA[4*u+0]);
            accA[4*u+1] = fmaf(xv, t4.y - b4.y, accA[4*u+1]);
            accA[4*u+2] = fmaf(xv, t4.z - b4.z, accA[4*u+2]);
            accA[4*u+3] = fmaf(xv, t4.w - b4.w, accA[4*u+3]);
            accC[4*u+0] = fmaf(xv, b4.x, accC[4*u+0]);
            accC[4*u+1] = fmaf(xv, b4.y, accC[4*u+1]);
            accC[4*u+2] = fmaf(xv, b4.z, accC[4*u+2]);
            accC[4*u+3] = fmaf(xv, b4.w, accC[4*u+3]);
        }
    }
    size_t rowo = (size_t)(nodeBase + node)*COUT + co;
    #pragma unroll
    for (int s = 0; s < STRIP; s++) {
        g_A[rowo + s] = accA[s] + bias[co + s];
        g_C[rowo + s] = accC[s];
    }
}

// ---------------- gather-max aggregate: out = A[i] + max_k C[knn(i,k)] ----------------
template<int COUT, int CATOFF>
__global__ void agg_kernel() {
    const int node = blockIdx.x;
    const int c = threadIdx.x;
    __shared__ int sidx[KK];
    if (c < KK) sidx[c] = g_knn[(size_t)node*KK + c];
    __syncthreads();
    const int jb = (node >> 12) << 12;   // batch base (NN = 4096)
    float m = -3.4e38f;
    #pragma unroll
    for (int k = 0; k < KK; k++)
        m = fmaxf(m, g_C[(size_t)(jb + sidx[k])*COUT + c]);
    g_xcat[(size_t)node*512 + CATOFF + c] = g_A[(size_t)node*COUT + c] + m;
}

// ---------------- final GEMM [BN,512]x[512,1024] fused with max over N ----------------
__global__ void __launch_bounds__(256) final_kernel(const float* __restrict__ Wf1,
                                                    const float* __restrict__ bf1) {
    __shared__ float As[16][132];   // [k][node]
    __shared__ float Bs[16][132];   // [k][out]
    __shared__ int cmax[128];

    const int tid = threadIdx.x;
    const int nodeBase = blockIdx.x * 128;
    const int outBase  = blockIdx.y * 128;
    const int rb = (tid >> 4) * 8;
    const int cb = (tid & 15) * 8;

    float acc[8][8];
    #pragma unroll
    for (int u = 0; u < 8; u++)
        #pragma unroll
        for (int v = 0; v < 8; v++) acc[u][v] = 0.f;

    for (int kc = 0; kc < 512; kc += 16) {
        __syncthreads();
        for (int e = tid; e < 128*16; e += 256) {
            int node = e >> 4, k = e & 15;
            As[k][node] = g_xcat[(size_t)(nodeBase + node)*512 + kc + k];
        }
        for (int e = tid; e < 16*128; e += 256) {
            int k = e >> 7, o = e & 127;
            Bs[k][o] = Wf1[(size_t)(kc + k)*1024 + outBase + o];
        }
        __syncthreads();
        #pragma unroll
        for (int k = 0; k < 16; k++) {
            float4 a0 = *reinterpret_cast<const float4*>(&As[k][rb]);
            float4 a1 = *reinterpret_cast<const float4*>(&As[k][rb+4]);
            float4 b0 = *reinterpret_cast<const float4*>(&Bs[k][cb]);
            float4 b1 = *reinterpret_cast<const float4*>(&Bs[k][cb+4]);
            float av[8] = {a0.x,a0.y,a0.z,a0.w,a1.x,a1.y,a1.z,a1.w};
            float bv[8] = {b0.x,b0.y,b0.z,b0.w,b1.x,b1.y,b1.z,b1.w};
            #pragma unroll
            for (int u = 0; u < 8; u++)
                #pragma unroll
                for (int v = 0; v < 8; v++) acc[u][v] = fmaf(av[u], bv[v], acc[u][v]);
        }
    }

    if (tid < 128) cmax[tid] = ENC_NEG_INF;
    __syncthreads();

    const int b = nodeBase >> 12;
    #pragma unroll
    for (int v = 0; v < 8; v++) {
        float colm = -3.4e38f;
        #pragma unroll
        for (int u = 0; u < 8; u++) colm = fmaxf(colm, acc[u][v]);
        colm += bf1[outBase + cb + v];
        atomicMax(&cmax[cb + v], encf(colm));
    }
    __syncthreads();
    if (tid < 128) atomicMax(&g_pool_enc[b*1024 + outBase + tid], cmax[tid]);
}

// ---------------- head ----------------
__global__ void head1_kernel(const float* __restrict__ Wa, const float* __restrict__ ba) {
    const int b = blockIdx.x, o = threadIdx.x;   // 512 threads
    __shared__ float p[1024];
    for (int e = o; e < 1024; e += 512) p[e] = decf(g_pool_enc[b*1024 + e]);
    __syncthreads();
    float acc = ba[o];
    #pragma unroll 8
    for (int in = 0; in < 1024; in++) acc = fmaf(p[in], Wa[(size_t)in*512 + o], acc);
    g_h1[b*512 + o] = fmaxf(acc, 0.f);
}

__global__ void head2_kernel(const float* __restrict__ Wb, const float* __restrict__ bb) {
    const int b = blockIdx.x, o = threadIdx.x;   // 256 threads
    __shared__ float p[512];
    for (int e = o; e < 512; e += 256) p[e] = g_h1[b*512 + e];
    __syncthreads();
    float acc = bb[o];
    #pragma unroll 8
    for (int in = 0; in < 512; in++) acc = fmaf(p[in], Wb[(size_t)in*256 + o], acc);
    g_h2[b*256 + o] = fmaxf(acc, 0.f);
}

__global__ void head3_kernel(const float* __restrict__ Wc, const float* __restrict__ bc,
                             float* __restrict__ out) {
    const int b = blockIdx.x, t = threadIdx.x;   // 32 threads
    __shared__ float h[256];
    for (int e = t; e < 256; e += 32) h[e] = g_h2[b*256 + e];
    __syncthreads();
    float logit = -3.4e38f;
    if (t < 23) {
        logit = bc[t];
        #pragma unroll 8
        for (int in = 0; in < 256; in++) logit = fmaf(h[in], Wc[in*23 + t], logit);
    }
    float mx = logit;
    #pragma unroll
    for (int off = 16; off > 0; off >>= 1) mx = fmaxf(mx, __shfl_xor_sync(0xffffffffu, mx, off));
    float ex = (t < 23) ? expf(logit - mx) : 0.f;
    float s = ex;
    #pragma unroll
    for (int off = 16; off > 0; off >>= 1) s += __shfl_xor_sync(0xffffffffu, s, off);
    if (t < 23) out[b*23 + t] = logit - mx - logf(s);
}

// ---------------- launch ----------------
extern "C" void kernel_launch(void* const* d_in, const int* in_sizes, int n_in,
                              void* d_out, int out_size) {
    const float* pos = (const float*)d_in[0];
    const float* x   = (const float*)d_in[1];
    const float* W1  = (const float*)d_in[2];  const float* b1 = (const float*)d_in[3];
    const float* W2  = (const float*)d_in[4];  const float* b2 = (const float*)d_in[5];
    const float* W3  = (const float*)d_in[6];  const float* b3 = (const float*)d_in[7];
    const float* W4  = (const float*)d_in[8];  const float* b4 = (const float*)d_in[9];
    const float* Wf1 = (const float*)d_in[10]; const float* bf1 = (const float*)d_in[11];
    const float* Wa  = (const float*)d_in[12]; const float* ba = (const float*)d_in[13];
    const float* Wb  = (const float*)d_in[14]; const float* bb = (const float*)d_in[15];
    const float* Wc  = (const float*)d_in[16]; const float* bc = (const float*)d_in[17];
    float* out = (float*)d_out;

    build_x0_kernel<<<(BN*6 + 255)/256, 256>>>(pos, x);
    init_pool_kernel<<<(BB*1024 + 255)/256, 256>>>();

    // layer 1: x0 (CIN=6, stride 6) -> x1 (64) @ cat offset 0
    sq_kernel<6, 6, true, 0><<<BN/256, 256>>>();
    knn_kernel<6, 6, true, 0><<<dim3(NN/128, BB), 128>>>();
    proj_kernel<6, 6, true, 0, 64><<<BN/16, 256>>>(W1, b1);
    agg_kernel<64, 0><<<BN, 64>>>();

    // layer 2: x1 (CIN=64, stride 512, off 0) -> x2 (64) @ cat offset 64
    sq_kernel<64, 512, false, 0><<<BN/256, 256>>>();
    knn_kernel<64, 512, false, 0><<<dim3(NN/128, BB), 128>>>();
    proj_kernel<64, 512, false, 0, 64><<<BN/16, 256>>>(W2, b2);
    agg_kernel<64, 64><<<BN, 64>>>();

    // layer 3: x2 (CIN=64, off 64) -> x3 (128) @ cat offset 128
    sq_kernel<64, 512, false, 64><<<BN/256, 256>>>();
    knn_kernel<64, 512, false, 64><<<dim3(NN/128, BB), 128>>>();
    proj_kernel<64, 512, false, 64, 128><<<BN/16, 256>>>(W3, b3);
    agg_kernel<128, 128><<<BN, 128>>>();

    // layer 4: x3 (CIN=128, off 128) -> x4 (256) @ cat offset 256
    sq_kernel<128, 512, false, 128><<<BN/256, 256>>>();
    knn_kernel<128, 512, false, 128><<<dim3(NN/128, BB), 128>>>();
    proj_kernel<128, 512, false, 128, 256><<<BN/16, 256>>>(W4, b4);
    agg_kernel<256, 256><<<BN, 256>>>();

    // final feature GEMM + global max-pool
    final_kernel<<<dim3(BN/128, 1024/128), 256>>>(Wf1, bf1);

    // head
    head1_kernel<<<BB, 512>>>(Wa, ba);
    head2_kernel<<<BB, 256>>>(Wb, bb);
    head3_kernel<<<BB, 32>>>(Wc, bc, out);
}

// round 5
// speedup vs baseline: 2.5048x; 2.5048x over previous
#include <cuda_runtime.h>
#include <math.h>

#define BB 8
#define NN 4096
#define KK 20
#define BN (BB*NN)

// ---------------- scratch (static device globals; no runtime alloc) ----------------
__device__ float g_x0[BN*6];
__device__ float g_xcat[(size_t)BN*512];
__device__ float g_A[(size_t)BN*256];
__device__ float g_C[(size_t)BN*256];
__device__ float g_sq[BN];
__device__ int   g_knn[BN*KK];
__device__ int   g_pool_enc[BB*1024];
__device__ float g_h1[BB*512];
__device__ float g_h2[BB*256];

__device__ __forceinline__ int   encf(float f){ int i=__float_as_int(f); return i>=0 ? i : i^0x7FFFFFFF; }
__device__ __forceinline__ float decf(int i){ return __int_as_float(i>=0 ? i : i^0x7FFFFFFF); }
#define ENC_NEG_INF (-2139095041)  /* encf(-inf) = 0x807FFFFF */

// ---------------- build x0 = concat(pos, x) ----------------
__global__ void build_x0_kernel(const float* __restrict__ pos, const float* __restrict__ x) {
    int g = blockIdx.x * 256 + threadIdx.x;
    if (g >= BN*6) return;
    int n = g / 6, c = g - n*6;
    g_x0[g] = (c < 3) ? pos[n*3 + c] : x[n*3 + c - 3];
}

__global__ void init_pool_kernel() {
    int g = blockIdx.x * 256 + threadIdx.x;
    if (g < BB*1024) g_pool_enc[g] = ENC_NEG_INF;
}

// ---------------- squared norms ----------------
template<int CIN, int SIN, bool USE_X0, int INOFF>
__global__ void sq_kernel() {
    int g = blockIdx.x * 256 + threadIdx.x;
    if (g >= BN) return;
    const float* base = USE_X0 ? g_x0 : (g_xcat + INOFF);
    const float* xr = base + (size_t)g * SIN;
    float s = 0.f;
    #pragma unroll 8
    for (int c = 0; c < CIN; c++) { float v = xr[c]; s += v*v; }
    g_sq[g] = s;
}

// ---------------- kNN: streaming top-20, register-resident sorted list ----------------
// One thread per node i (64 per block). xi rows staged in shared (padded,
// conflict-free). Top-20 kept in REGISTERS via a fully-unrolled static-index
// compare-exchange insertion (no dynamic local-array indexing -> no LDL/STL).
template<int CIN, int SIN, bool USE_X0, int INOFF>
__global__ void __launch_bounds__(64, 8) knn_kernel() {
    constexpr int TI = 64;
    constexpr int TJ = 16;
    const int b   = blockIdx.y;
    const int tid = threadIdx.x;
    const int i   = blockIdx.x * TI + tid;
    const float* base = USE_X0 ? g_x0 : (g_xcat + INOFF);
    const float* Xb = base + (size_t)b * NN * SIN;

    __shared__ float Xis[TI][CIN+1];   // +1 pad: odd stride -> conflict-free scalar LDS
    __shared__ float Xjs[TJ][CIN];
    __shared__ float sqj[TJ];

    // stage this block's 64 xi rows into shared (coalesced)
    for (int e = tid; e < TI*CIN; e += TI) {
        int r = e / CIN, c = e - r*CIN;
        Xis[r][c] = Xb[(size_t)(blockIdx.x*TI + r)*SIN + c];
    }

    float kd[KK]; int ki[KK];
    #pragma unroll
    for (int k = 0; k < KK; k++) { kd[k] = 3.4e38f; ki[k] = 0; }
    float worst = 3.4e38f;

    const float sqi = g_sq[b*NN + i];

    for (int jb = 0; jb < NN; jb += TJ) {
        __syncthreads();   // covers Xis staging on first iter + tile reuse after
        for (int e = tid; e < TJ*CIN; e += TI) {
            int r = e / CIN, c = e - r*CIN;
            Xjs[r][c] = Xb[(size_t)(jb + r)*SIN + c];
        }
        if (tid < TJ) sqj[tid] = g_sq[b*NN + jb + tid];
        __syncthreads();

        float acc[TJ];
        #pragma unroll
        for (int j = 0; j < TJ; j++) acc[j] = 0.f;

        if (CIN % 4 == 0) {
            #pragma unroll 4
            for (int c4 = 0; c4 < CIN/4; c4++) {
                const float a0 = Xis[tid][c4*4+0];
                const float a1 = Xis[tid][c4*4+1];
                const float a2 = Xis[tid][c4*4+2];
                const float a3 = Xis[tid][c4*4+3];
                #pragma unroll
                for (int j = 0; j < TJ; j++) {
                    const float4 b4 = *reinterpret_cast<const float4*>(&Xjs[j][c4*4]);
                    acc[j] = fmaf(a0, b4.x, acc[j]);
                    acc[j] = fmaf(a1, b4.y, acc[j]);
                    acc[j] = fmaf(a2, b4.z, acc[j]);
                    acc[j] = fmaf(a3, b4.w, acc[j]);
                }
            }
        } else {
            #pragma unroll
            for (int c = 0; c < CIN; c++) {
                const float xv = Xis[tid][c];
                #pragma unroll
                for (int j = 0; j < TJ; j++) acc[j] = fmaf(xv, Xjs[j][c], acc[j]);
            }
        }

        #pragma unroll
        for (int j = 0; j < TJ; j++) {
            float d = sqi + sqj[j] - 2.f*acc[j];
            if (d < worst) {
                // static-index rolling insert into ascending-sorted list
                float cd = d; int ci = jb + j;
                #pragma unroll
                for (int k = 0; k < KK; k++) {
                    const bool sw = cd < kd[k];
                    const float nd = sw ? kd[k] : cd;
                    const int   ni = sw ? ki[k] : ci;
                    kd[k] = sw ? cd : kd[k];
                    ki[k] = sw ? ci : ki[k];
                    cd = nd; ci = ni;
                }
                worst = kd[KK-1];
            }
        }
    }

    int* dst = g_knn + (size_t)(b*NN + i)*KK;
    #pragma unroll
    for (int k = 0; k < KK; k++) dst[k] = ki[k];
}

// ---------------- per-node projections: A = X(Wt-Wb)+b, C = X Wb ----------------
template<int CIN, int SIN, bool USE_X0, int INOFF, int COUT>
__global__ void __launch_bounds__(256) proj_kernel(const float* __restrict__ W,
                                                   const float* __restrict__ bias) {
    constexpr int TM = 16;
    constexpr int STRIP = COUT / 16;        // 4, 8, or 16 (all %4==0)
    __shared__ float xs[TM][CIN];

    const int nodeBase = blockIdx.x * TM;
    const int tid = threadIdx.x;
    const float* base = USE_X0 ? g_x0 : (g_xcat + INOFF);

    for (int e = tid; e < TM*CIN; e += 256) {
        int r = e / CIN, c = e - r*CIN;
        xs[r][c] = base[(size_t)(nodeBase + r)*SIN + c];
    }
    __syncthreads();

    const int node = tid >> 4;
    const int cg   = tid & 15;
    const int co   = cg * STRIP;

    float accA[STRIP], accC[STRIP];
    #pragma unroll
    for (int s = 0; s < STRIP; s++) { accA[s] = 0.f; accC[s] = 0.f; }

    #pragma unroll 4
    for (int c = 0; c < CIN; c++) {
        float xv = xs[node][c];
        const float4* wt = reinterpret_cast<const float4*>(W + (size_t)c*COUT + co);
        const float4* wb = reinterpret_cast<const float4*>(W + (size_t)(CIN + c)*COUT + co);
        #pragma unroll
        for (int u = 0; u < STRIP/4; u++) {
            float4 t4 = __ldg(wt + u);
            float4 b4 = __ldg(wb + u);
            accA[4*u+0] = fmaf(xv, t4.x - b4.x, accA[4*u+0]);
            accA[4*u+1] = fmaf(xv, t4.y - b4.y, accA[4*u+1]);
            accA[4*u+2] = fmaf(xv, t4.z - b4.z, accA[4*u+2]);
            accA[4*u+3] = fmaf(xv, t4.w - b4.w, accA[4*u+3]);
            accC[4*u+0] = fmaf(xv, b4.x, accC[4*u+0]);
            accC[4*u+1] = fmaf(xv, b4.y, accC[4*u+1]);
            accC[4*u+2] = fmaf(xv, b4.z, accC[4*u+2]);
            accC[4*u+3] = fmaf(xv, b4.w, accC[4*u+3]);
        }
    }
    size_t rowo = (size_t)(nodeBase + node)*COUT + co;
    #pragma unroll
    for (int s = 0; s < STRIP; s++) {
        g_A[rowo + s] = accA[s] + bias[co + s];
        g_C[rowo + s] = accC[s];
    }
}

// ---------------- gather-max aggregate: out = A[i] + max_k C[knn(i,k)] ----------------
template<int COUT, int CATOFF>
__global__ void agg_kernel() {
    const int node = blockIdx.x;
    const int c = threadIdx.x;
    __shared__ int sidx[KK];
    if (c < KK) sidx[c] = g_knn[(size_t)node*KK + c];
    __syncthreads();
    const int jb = (node >> 12) << 12;   // batch base (NN = 4096)
    float m = -3.4e38f;
    #pragma unroll
    for (int k = 0; k < KK; k++)
        m = fmaxf(m, g_C[(size_t)(jb + sidx[k])*COUT + c]);
    g_xcat[(size_t)node*512 + CATOFF + c] = g_A[(size_t)node*COUT + c] + m;
}

// ---------------- final GEMM [BN,512]x[512,1024] fused with max over N ----------------
__global__ void __launch_bounds__(256) final_kernel(const float* __restrict__ Wf1,
                                                    const float* __restrict__ bf1) {
    __shared__ float As[16][132];   // [k][node]
    __shared__ float Bs[16][132];   // [k][out]
    __shared__ int cmax[128];

    const int tid = threadIdx.x;
    const int nodeBase = blockIdx.x * 128;
    const int outBase  = blockIdx.y * 128;
    const int rb = (tid >> 4) * 8;
    const int cb = (tid & 15) * 8;

    float acc[8][8];
    #pragma unroll
    for (int u = 0; u < 8; u++)
        #pragma unroll
        for (int v = 0; v < 8; v++) acc[u][v] = 0.f;

    for (int kc = 0; kc < 512; kc += 16) {
        __syncthreads();
        for (int e = tid; e < 128*16; e += 256) {
            int node = e >> 4, k = e & 15;
            As[k][node] = g_xcat[(size_t)(nodeBase + node)*512 + kc + k];
        }
        for (int e = tid; e < 16*128; e += 256) {
            int k = e >> 7, o = e & 127;
            Bs[k][o] = Wf1[(size_t)(kc + k)*1024 + outBase + o];
        }
        __syncthreads();
        #pragma unroll
        for (int k = 0; k < 16; k++) {
            float4 a0 = *reinterpret_cast<const float4*>(&As[k][rb]);
            float4 a1 = *reinterpret_cast<const float4*>(&As[k][rb+4]);
            float4 b0 = *reinterpret_cast<const float4*>(&Bs[k][cb]);
            float4 b1 = *reinterpret_cast<const float4*>(&Bs[k][cb+4]);
            float av[8] = {a0.x,a0.y,a0.z,a0.w,a1.x,a1.y,a1.z,a1.w};
            float bv[8] = {b0.x,b0.y,b0.z,b0.w,b1.x,b1.y,b1.z,b1.w};
            #pragma unroll
            for (int u = 0; u < 8; u++)
                #pragma unroll
                for (int v = 0; v < 8; v++) acc[u][v] = fmaf(av[u], bv[v], acc[u][v]);
        }
    }

    if (tid < 128) cmax[tid] = ENC_NEG_INF;
    __syncthreads();

    const int b = nodeBase >> 12;
    #pragma unroll
    for (int v = 0; v < 8; v++) {
        float colm = -3.4e38f;
        #pragma unroll
        for (int u = 0; u < 8; u++) colm = fmaxf(colm, acc[u][v]);
        colm += bf1[outBase + cb + v];
        atomicMax(&cmax[cb + v], encf(colm));
    }
    __syncthreads();
    if (tid < 128) atomicMax(&g_pool_enc[b*1024 + outBase + tid], cmax[tid]);
}

// ---------------- head ----------------
__global__ void head1_kernel(const float* __restrict__ Wa, const float* __restrict__ ba) {
    const int b = blockIdx.x, o = threadIdx.x;   // 512 threads
    __shared__ float p[1024];
    for (int e = o; e < 1024; e += 512) p[e] = decf(g_pool_enc[b*1024 + e]);
    __syncthreads();
    float acc = ba[o];
    #pragma unroll 8
    for (int in = 0; in < 1024; in++) acc = fmaf(p[in], Wa[(size_t)in*512 + o], acc);
    g_h1[b*512 + o] = fmaxf(acc, 0.f);
}

__global__ void head2_kernel(const float* __restrict__ Wb, const float* __restrict__ bb) {
    const int b = blockIdx.x, o = threadIdx.x;   // 256 threads
    __shared__ float p[512];
    for (int e = o; e < 512; e += 256) p[e] = g_h1[b*512 + e];
    __syncthreads();
    float acc = bb[o];
    #pragma unroll 8
    for (int in = 0; in < 512; in++) acc = fmaf(p[in], Wb[(size_t)in*256 + o], acc);
    g_h2[b*256 + o] = fmaxf(acc, 0.f);
}

__global__ void head3_kernel(const float* __restrict__ Wc, const float* __restrict__ bc,
                             float* __restrict__ out) {
    const int b = blockIdx.x, t = threadIdx.x;   // 32 threads
    __shared__ float h[256];
    for (int e = t; e < 256; e += 32) h[e] = g_h2[b*256 + e];
    __syncthreads();
    float logit = -3.4e38f;
    if (t < 23) {
        logit = bc[t];
        #pragma unroll 8
        for (int in = 0; in < 256; in++) logit = fmaf(h[in], Wc[in*23 + t], logit);
    }
    float mx = logit;
    #pragma unroll
    for (int off = 16; off > 0; off >>= 1) mx = fmaxf(mx, __shfl_xor_sync(0xffffffffu, mx, off));
    float ex = (t < 23) ? expf(logit - mx) : 0.f;
    float s = ex;
    #pragma unroll
    for (int off = 16; off > 0; off >>= 1) s += __shfl_xor_sync(0xffffffffu, s, off);
    if (t < 23) out[b*23 + t] = logit - mx - logf(s);
}

// ---------------- launch ----------------
extern "C" void kernel_launch(void* const* d_in, const int* in_sizes, int n_in,
                              void* d_out, int out_size) {
    const float* pos = (const float*)d_in[0];
    const float* x   = (const float*)d_in[1];
    const float* W1  = (const float*)d_in[2];  const float* b1 = (const float*)d_in[3];
    const float* W2  = (const float*)d_in[4];  const float* b2 = (const float*)d_in[5];
    const float* W3  = (const float*)d_in[6];  const float* b3 = (const float*)d_in[7];
    const float* W4  = (const float*)d_in[8];  const float* b4 = (const float*)d_in[9];
    const float* Wf1 = (const float*)d_in[10]; const float* bf1 = (const float*)d_in[11];
    const float* Wa  = (const float*)d_in[12]; const float* ba = (const float*)d_in[13];
    const float* Wb  = (const float*)d_in[14]; const float* bb = (const float*)d_in[15];
    const float* Wc  = (const float*)d_in[16]; const float* bc = (const float*)d_in[17];
    float* out = (float*)d_out;

    build_x0_kernel<<<(BN*6 + 255)/256, 256>>>(pos, x);
    init_pool_kernel<<<(BB*1024 + 255)/256, 256>>>();

    // layer 1: x0 (CIN=6, stride 6) -> x1 (64) @ cat offset 0
    sq_kernel<6, 6, true, 0><<<BN/256, 256>>>();
    knn_kernel<6, 6, true, 0><<<dim3(NN/64, BB), 64>>>();
    proj_kernel<6, 6, true, 0, 64><<<BN/16, 256>>>(W1, b1);
    agg_kernel<64, 0><<<BN, 64>>>();

    // layer 2: x1 (CIN=64, stride 512, off 0) -> x2 (64) @ cat offset 64
    sq_kernel<64, 512, false, 0><<<BN/256, 256>>>();
    knn_kernel<64, 512, false, 0><<<dim3(NN/64, BB), 64>>>();
    proj_kernel<64, 512, false, 0, 64><<<BN/16, 256>>>(W2, b2);
    agg_kernel<64, 64><<<BN, 64>>>();

    // layer 3: x2 (CIN=64, off 64) -> x3 (128) @ cat offset 128
    sq_kernel<64, 512, false, 64><<<BN/256, 256>>>();
    knn_kernel<64, 512, false, 64><<<dim3(NN/64, BB), 64>>>();
    proj_kernel<64, 512, false, 64, 128><<<BN/16, 256>>>(W3, b3);
    agg_kernel<128, 128><<<BN, 128>>>();

    // layer 4: x3 (CIN=128, off 128) -> x4 (256) @ cat offset 256
    sq_kernel<128, 512, false, 128><<<BN/256, 256>>>();
    knn_kernel<128, 512, false, 128><<<dim3(NN/64, BB), 64>>>();
    proj_kernel<128, 512, false, 128, 256><<<BN/16, 256>>>(W4, b4);
    agg_kernel<256, 256><<<BN, 256>>>();

    // final feature GEMM + global max-pool
    final_kernel<<<dim3(BN/128, 1024/128), 256>>>(Wf1, bf1);

    // head
    head1_kernel<<<BB, 512>>>(Wa, ba);
    head2_kernel<<<BB, 256>>>(Wb, bb);
    head3_kernel<<<BB, 32>>>(Wc, bc, out);
}